// round 4
// baseline (speedup 1.0000x reference)
#include <cuda_runtime.h>

#define HH    640
#define WW    640
#define BATCH 4
#define NLAB  10
#define NPIX  (HH*WW)
#define STRIP_H 10
#define WPB   2                         // warps per block
#define BLK_ROWS (STRIP_H*WPB)          // 20
#define NBANDS (HH/BLK_ROWS)            // 32
#define GXS   (WW/128)                  // 5 col strips
#define NBLOCKS (GXS*(NBANDS+1)*BATCH)  // 660 (includes edge blocks)

__device__ float d_accIn[BATCH];
__device__ float d_accGrad[BATCH];
__device__ float d_boxF[BATCH*NLAB];
__device__ float d_boxE[BATCH*NLAB];
__device__ unsigned d_count;

__device__ __forceinline__ float wsum(float v) {
    #pragma unroll
    for (int o = 16; o; o >>= 1) v += __shfl_down_sync(0xffffffffu, v, o);
    return v;
}

// One image row per array: float4 + warp shuffles for the +/-1 columns.
__device__ __forceinline__ void loadrow(const float* __restrict__ p, int rowOff, bool rowIn,
                                        int c0, int lane, float* t1, float* t2, float* raw)
{
    float4 q = make_float4(0.f, 0.f, 0.f, 0.f);
    if (rowIn) q = *reinterpret_cast<const float4*>(p + rowOff + c0);
    float left  = __shfl_up_sync(0xffffffffu, q.w, 1);
    float right = __shfl_down_sync(0xffffffffu, q.x, 1);
    if (lane == 0)  left  = (rowIn && c0 > 0)      ? p[rowOff + c0 - 1] : 0.f;
    if (lane == 31) right = (rowIn && c0 + 4 < WW) ? p[rowOff + c0 + 4] : 0.f;
    t1[0] = left + 2.f*q.x + q.y;  t1[1] = q.x + 2.f*q.y + q.z;
    t1[2] = q.y + 2.f*q.z + q.w;   t1[3] = q.z + 2.f*q.w + right;
    t2[0] = q.y - left;  t2[1] = q.z - q.x;  t2[2] = q.w - q.y;  t2[3] = right - q.z;
    raw[0] = q.x; raw[1] = q.y; raw[2] = q.z; raw[3] = q.w;
}

__device__ __forceinline__ float combineF(float gxV, float gyV, float gxT, float gyT,
                                          float gxG, float gyG)
{
    float gradV = fabsf(gxV) + fabsf(gyV);
    float g7 = fabsf(0.3f*gxV + 0.7f*gxT) + fabsf(0.3f*gyV + 0.7f*gyT);
    float gradG = fabsf(gxG) + fabsf(gyG);
    return fabsf(gradG - fmaxf(gradV, g7));
}

// Full masked 3x3 sobel F at (r,c) from global memory (box vertical edges only).
__device__ __noinline__ float maskedF_g(const float* __restrict__ vis, const float* __restrict__ th,
                                        const float* __restrict__ gen, int base, int r, int c, int4 B)
{
    float v[8], t[8], g[8];
    const int dr[8] = {-1,-1,-1, 0, 0, 1, 1, 1};
    const int dc[8] = {-1, 0, 1,-1, 1,-1, 0, 1};
    #pragma unroll
    for (int i = 0; i < 8; i++) {
        int rr = r + dr[i], cc = c + dc[i];
        bool in = (rr >= B.y) & (rr < B.w) & (cc >= B.x) & (cc < B.z);
        int q = in ? base + rr * WW + cc : base;
        float m = in ? 1.f : 0.f;
        v[i] = vis[q] * m; t[i] = th[q] * m; g[i] = gen[q] * m;
    }
    // idx: 0=TL 1=T 2=TR 3=L 4=R 5=BL 6=B 7=BR
    float gxV = (v[2]-v[0]) + 2.f*(v[4]-v[3]) + (v[7]-v[5]);
    float gyV = (v[0]-v[5]) + 2.f*(v[1]-v[6]) + (v[2]-v[7]);
    float gxT = (t[2]-t[0]) + 2.f*(t[4]-t[3]) + (t[7]-t[5]);
    float gyT = (t[0]-t[5]) + 2.f*(t[1]-t[6]) + (t[2]-t[7]);
    float gxG = (g[2]-g[0]) + 2.f*(g[4]-g[3]) + (g[7]-g[5]);
    float gyG = (g[0]-g[5]) + 2.f*(g[1]-g[6]) + (g[2]-g[7]);
    return combineF(gxV, gyV, gxT, gyT, gxG, gyG);
}

__global__ __launch_bounds__(32*WPB) void fused_k(
    const float* __restrict__ vis, const float* __restrict__ th,
    const float* __restrict__ gen, const int* __restrict__ label,
    const float* __restrict__ bptr, const float* __restrict__ cptr,
    float* __restrict__ out)
{
    __shared__ int4  sBox[NLAB];
    __shared__ int   sBoxIdx[NLAB];
    __shared__ int   sN;
    __shared__ int   sIsLast;
    __shared__ float sLs[BATCH*NLAB], sL1[BATCH*NLAB];

    const int lane = threadIdx.x, w = threadIdx.y;
    const int tid = w * 32 + lane;
    const int bz = blockIdx.z;
    const int base = bz * NPIX;

    if (blockIdx.y < NBANDS) {
        // ---------------- main streaming-stencil path ----------------
        const int strip = blockIdx.x;
        const int c0 = strip * 128 + lane * 4;
        const int r0 = blockIdx.y * BLK_ROWS + w * STRIP_H;

        if (tid == 0) sN = 0;
        __syncthreads();
        if (tid < NLAB) {
            const int* L = label + (bz * NLAB + tid) * 5;
            int x1 = L[1], y1 = L[2], x2 = L[3], y2 = L[4];
            int rb0 = blockIdx.y * BLK_ROWS;
            if (x2 > x1 && y2 > y1 &&
                x1 < strip * 128 + 128 && x2 > strip * 128 &&
                y1 < rb0 + BLK_ROWS && y2 > rb0) {
                int p = atomicAdd(&sN, 1);
                sBox[p] = make_int4(x1, y1, x2, y2);
                sBoxIdx[p] = bz * NLAB + tid;
            }
        }
        __syncthreads();
        const int nOv = sN;

        float A0x[3][4], A0y[3][4], A1x[3][4], A1y[3][4];
        float midA[3][4], midB[3][4];
        float fbL[NLAB], ebL[NLAB];
        for (int b = 0; b < nOv; b++) { fbL[b] = 0.f; ebL[b] = 0.f; }
        float li = 0.f, lg = 0.f;

        { // prologue: rows r0-1 (top) and r0 (mid)
            float tp1[3][4], tp2[3][4], dum[3][4];
            float t1[3][4], t2[3][4];
            bool in0 = (r0 - 1) >= 0;
            loadrow(vis, base + (r0-1)*WW, in0, c0, lane, tp1[0], tp2[0], dum[0]);
            loadrow(th , base + (r0-1)*WW, in0, c0, lane, tp1[1], tp2[1], dum[1]);
            loadrow(gen, base + (r0-1)*WW, in0, c0, lane, tp1[2], tp2[2], dum[2]);
            loadrow(vis, base + r0*WW, true, c0, lane, t1[0], t2[0], midA[0]);
            loadrow(th , base + r0*WW, true, c0, lane, t1[1], t2[1], midA[1]);
            loadrow(gen, base + r0*WW, true, c0, lane, t1[2], t2[2], midA[2]);
            #pragma unroll
            for (int a = 0; a < 3; a++)
            #pragma unroll
            for (int k = 0; k < 4; k++) {
                A0x[a][k] = tp2[a][k] + 2.f*t2[a][k];  // top + mid (for out r0)
                A0y[a][k] = tp1[a][k];
                A1x[a][k] = t2[a][k];                  // top (for out r0+1)
                A1y[a][k] = t1[a][k];
            }
        }

        auto step = [&](float (&P0x)[3][4], float (&P0y)[3][4],
                        float (&P1x)[3][4], float (&P1y)[3][4],
                        float (&rawM)[3][4], float (&rawN)[3][4], int r)
        {
            float t1[3][4], t2[3][4];
            int rn = r + 1;
            bool rowIn = rn < HH;
            int rowOff = base + rn * WW;
            loadrow(vis, rowOff, rowIn, c0, lane, t1[0], t2[0], rawN[0]);
            loadrow(th , rowOff, rowIn, c0, lane, t1[1], t2[1], rawN[1]);
            loadrow(gen, rowOff, rowIn, c0, lane, t1[2], t2[2], rawN[2]);

            float gxs[3][4], gys[3][4];
            #pragma unroll
            for (int a = 0; a < 3; a++)
            #pragma unroll
            for (int k = 0; k < 4; k++) {
                gxs[a][k] = P0x[a][k] + t2[a][k];
                gys[a][k] = P0y[a][k] - t1[a][k];
            }

            float F[4], E[4];
            #pragma unroll
            for (int k = 0; k < 4; k++) {
                float gradV = fabsf(gxs[0][k]) + fabsf(gys[0][k]);
                float gradG = fabsf(gxs[2][k]) + fabsf(gys[2][k]);
                float g5 = fabsf(0.5f*(gxs[0][k]+gxs[1][k])) + fabsf(0.5f*(gys[0][k]+gys[1][k]));
                float g7 = fabsf(0.3f*gxs[0][k]+0.7f*gxs[1][k]) + fabsf(0.3f*gys[0][k]+0.7f*gys[1][k]);
                float v = rawM[0][k], t = rawM[1][k], g = rawM[2][k];
                li += fabsf(g - fmaxf(v, 0.5f*(v + t)));
                lg += fabsf(gradG - fmaxf(gradV, g5));
                F[k] = fabsf(gradG - fmaxf(gradV, g7));
                E[k] = fabsf(g - fmaxf(v, 0.3f*v + 0.7f*t));
            }

            // per-box sums (before acc update so P1x == t2 of mid row r)
            for (int b = 0; b < nOv; b++) {
                int4 B = sBox[b];
                if (r < B.y || r >= B.w) continue;
                bool top = r > B.y, bot = r < B.w - 1;
                bool rowInt = top & bot;
                float fAdd = 0.f, eAdd = 0.f;
                #pragma unroll
                for (int k = 0; k < 4; k++) {
                    int c = c0 + k;
                    if (c < B.x || c >= B.z) continue;
                    eAdd += E[k];
                    if (c > B.x && c < B.z - 1) {     // col-edge F handled by edge blocks
                        if (rowInt) fAdd += F[k];
                        else {
                            float mgx[3], mgy[3];
                            #pragma unroll
                            for (int a = 0; a < 3; a++) {
                                mgx[a] = (top ? P0x[a][k] : 2.f*P1x[a][k]) + (bot ? t2[a][k] : 0.f);
                                mgy[a] = (top ? P0y[a][k] : 0.f) - (bot ? t1[a][k] : 0.f);
                            }
                            fAdd += combineF(mgx[0],mgy[0],mgx[1],mgy[1],mgx[2],mgy[2]);
                        }
                    }
                }
                fbL[b] += fAdd; ebL[b] += eAdd;
            }

            #pragma unroll
            for (int a = 0; a < 3; a++)
            #pragma unroll
            for (int k = 0; k < 4; k++) {
                P1x[a][k] += 2.f*t2[a][k];  // add mid for out r+1
                P0x[a][k] = t2[a][k];       // top for out r+2
                P0y[a][k] = t1[a][k];
            }
        };

        for (int i = 0; i < STRIP_H; i += 2) {
            step(A0x, A0y, A1x, A1y, midA, midB, r0 + i);
            step(A1x, A1y, A0x, A0y, midB, midA, r0 + i + 1);
        }

        li = wsum(li); lg = wsum(lg);
        if (lane == 0) {
            atomicAdd(&d_accIn[bz], li);
            atomicAdd(&d_accGrad[bz], lg);
        }
        for (int b = 0; b < nOv; b++) {
            float f = wsum(fbL[b]), e = wsum(ebL[b]);
            if (lane == 0) {
                atomicAdd(&d_boxF[sBoxIdx[b]], f);
                atomicAdd(&d_boxE[sBoxIdx[b]], e);
            }
        }
    } else {
        // ---------------- box vertical-edge pass (full masked sobel) ----------------
        int b = blockIdx.x * WPB + w;    // 0..9
        if (b < NLAB) {
            const int* L = label + (bz * NLAB + b) * 5;
            int4 B = make_int4(L[1], L[2], L[3], L[4]);
            if (B.z > B.x && B.w > B.y) {
                float sF = 0.f;
                int ncols = (B.z - 1 > B.x) ? 2 : 1;
                for (int ci = 0; ci < ncols; ci++) {
                    int c = ci ? B.z - 1 : B.x;
                    for (int r = B.y + lane; r < B.w; r += 32)
                        sF += maskedF_g(vis, th, gen, base, r, c, B);
                }
                sF = wsum(sF);
                if (lane == 0) atomicAdd(&d_boxF[bz * NLAB + b], sF);
            }
        }
    }

    // ---------------- last-block finalize ----------------
    __threadfence();
    __syncthreads();
    if (tid == 0) {
        unsigned o = atomicAdd(&d_count, 1u);
        sIsLast = (o == NBLOCKS - 1);
    }
    __syncthreads();
    if (!sIsLast) return;

    if (tid < BATCH * NLAB) {
        const int* L = label + tid * 5;
        int x1 = L[1], y1 = L[2], x2 = L[3], y2 = L[4];
        bool valid = !(x1 == 0 && y1 == 0 && x2 == 0 && y2 == 0);
        float area = (float)((y2 - y1) * (x2 - x1));   // C == 1
        float sa = fmaxf(area, 1.f);
        volatile float* vF = (volatile float*)d_boxF;
        volatile float* vE = (volatile float*)d_boxE;
        float f = vF[tid], e = vE[tid];
        float vv = valid ? 1.f : 0.f;
        sLs[tid] = (f / sa) * vv;
        sL1[tid] = (e / sa) * vv;
        d_boxF[tid] = 0.f; d_boxE[tid] = 0.f;          // reset for next replay
    }
    __syncthreads();
    if (tid < BATCH) {
        volatile float* aI = (volatile float*)d_accIn;
        volatile float* aG = (volatile float*)d_accGrad;
        const float inv = 1.0f / (float)NPIX;          // C == 1
        float loss_in   = aI[tid] * inv;
        float loss_grad = aG[tid] * inv;
        d_accIn[tid] = 0.f; d_accGrad[tid] = 0.f;

        float sLsum = 0.f, s1sum = 0.f, cnt = 0.f;
        for (int n = 0; n < NLAB; n++) {
            float a = sLs[tid * NLAB + n], bb = sL1[tid * NLAB + n];
            sLsum += a; s1sum += bb;
            if (a != 0.f || bb != 0.f) cnt += 1.f;
        }
        float safe_cnt = fmaxf(cnt, 1.f);
        float ls  = (cnt > 0.f) ? sLsum / safe_cnt : 0.f;
        float lin = (cnt > 0.f) ? s1sum / safe_cnt : 0.f;
        float alpha = *bptr, beta = *cptr;
        out[0*BATCH + tid] = 0.f;
        out[1*BATCH + tid] = alpha * loss_in + (1.f - alpha) * loss_grad;
        out[2*BATCH + tid] = (1.f - beta) * ls + beta * lin;
        out[3*BATCH + tid] = loss_in;
        out[4*BATCH + tid] = loss_grad;
        out[5*BATCH + tid] = ls;
        out[6*BATCH + tid] = lin;
    }
    if (tid == 0) d_count = 0;
}

extern "C" void kernel_launch(void* const* d_in, const int* in_sizes, int n_in,
                              void* d_out, int out_size)
{
    (void)in_sizes; (void)n_in; (void)out_size;
    const float* bptr  = (const float*)d_in[0];
    const float* cptr  = (const float*)d_in[1];
    const float* vis   = (const float*)d_in[2];
    // d_in[3] = image_ir (unused by the reference)
    const float* gen   = (const float*)d_in[4];
    const int*   label = (const int*)d_in[5];
    const float* th    = (const float*)d_in[6];
    float* out = (float*)d_out;

    dim3 grid(GXS, NBANDS + 1, BATCH);
    dim3 blk(32, WPB);
    fused_k<<<grid, blk>>>(vis, th, gen, label, bptr, cptr, out);
}

// round 5
// speedup vs baseline: 1.3034x; 1.3034x over previous
#include <cuda_runtime.h>

#define HH    640
#define WW    640
#define BATCH 4
#define NLAB  10
#define NPIX  (HH*WW)
#define TILE_W 128
#define TILE_H 16
#define GXB (WW/TILE_W)            // 5
#define GYB (HH/TILE_H)            // 40
#define NBLOCKS (GXB*GYB*BATCH)    // 800

// Persistent accumulators (zero-initialized at load; kernel restores zeros each call)
__device__ float d_accIn[BATCH];
__device__ float d_accGrad[BATCH];
__device__ float d_boxF[BATCH*NLAB];
__device__ float d_boxE[BATCH*NLAB];
__device__ unsigned d_count;

__device__ __forceinline__ float wsum(float v) {
    #pragma unroll
    for (int o = 16; o; o >>= 1) v += __shfl_down_sync(0xffffffffu, v, o);
    return v;
}

struct G4 { float gx[4], gy[4], c[4]; };

// Separable sobel for a 1x4 output strip from a shared tile (center smem row = ty+1).
__device__ __forceinline__ G4 sobel4(const float sm[TILE_H+2][132], int ty, int lc0) {
    G4 o;
    float t1[3][4], t2[3][4];
    #pragma unroll
    for (int r = 0; r < 3; r++) {
        const float* row = &sm[ty + r][lc0];
        float4 a = *reinterpret_cast<const float4*>(row);
        float2 b = *reinterpret_cast<const float2*>(row + 4);
        float v0=a.x, v1=a.y, v2=a.z, v3=a.w, v4=b.x, v5=b.y;
        t1[r][0]=v0+2.f*v1+v2; t1[r][1]=v1+2.f*v2+v3;
        t1[r][2]=v2+2.f*v3+v4; t1[r][3]=v3+2.f*v4+v5;
        t2[r][0]=v2-v0; t2[r][1]=v3-v1; t2[r][2]=v4-v2; t2[r][3]=v5-v3;
        if (r == 1) { o.c[0]=v1; o.c[1]=v2; o.c[2]=v3; o.c[3]=v4; }
    }
    #pragma unroll
    for (int k = 0; k < 4; k++) {
        o.gx[k] = t2[0][k] + 2.f*t2[1][k] + t2[2][k];
        o.gy[k] = t1[0][k] - t1[2][k];
    }
    return o;
}

// Exact masked sobel F at a ring pixel, from the shared tiles (halo covers ±1).
__device__ float maskedF(const float sV[TILE_H+2][132], const float sT[TILE_H+2][132],
                         const float sG[TILE_H+2][132], int ty, int lcc,
                         int r, int c, int4 B)
{
    const float wx[3][3] = {{-1,0,1},{-2,0,2},{-1,0,1}};
    const float wy[3][3] = {{1,2,1},{0,0,0},{-1,-2,-1}};
    float gxV=0,gyV=0,gxT=0,gyT=0,gxG=0,gyG=0;
    #pragma unroll
    for (int dr = 0; dr < 3; dr++)
    #pragma unroll
    for (int dc = 0; dc < 3; dc++) {
        int rr = r + dr - 1, cc = c + dc - 1;
        bool in = (rr >= B.y) & (rr < B.w) & (cc >= B.x) & (cc < B.z);
        float m = in ? 1.f : 0.f;
        float fv = sV[ty + dr][lcc - 1 + dc] * m;
        float ft = sT[ty + dr][lcc - 1 + dc] * m;
        float fg = sG[ty + dr][lcc - 1 + dc] * m;
        gxV += wx[dr][dc] * fv; gyV += wy[dr][dc] * fv;
        gxT += wx[dr][dc] * ft; gyT += wy[dr][dc] * ft;
        gxG += wx[dr][dc] * fg; gyG += wy[dr][dc] * fg;
    }
    float gradV = fabsf(gxV) + fabsf(gyV);
    float grad7 = fabsf(0.3f*gxV + 0.7f*gxT) + fabsf(0.3f*gyV + 0.7f*gyT);
    float gradG = fabsf(gxG) + fabsf(gyG);
    return fabsf(gradG - fmaxf(gradV, grad7));
}

__global__ __launch_bounds__(256) void fused_k(
    const float* __restrict__ vis, const float* __restrict__ th,
    const float* __restrict__ gen, const int* __restrict__ label,
    const float* __restrict__ bptr, const float* __restrict__ cptr,
    float* __restrict__ out)
{
    __shared__ float sV[TILE_H+2][132], sT[TILE_H+2][132], sG[TILE_H+2][132];
    __shared__ int4  sBox[NLAB];
    __shared__ int   sBoxIdx[NLAB];
    __shared__ float sAF[NLAB], sAE[NLAB];
    __shared__ int   sN;
    __shared__ int   sIsLast;
    __shared__ float sLs[BATCH*NLAB], sL1[BATCH*NLAB];

    const int tx = threadIdx.x, ty = threadIdx.y;
    const int tid = ty * 32 + tx;
    const int bz = blockIdx.z;
    const int colStart = blockIdx.x * TILE_W;
    const int rowStart = blockIdx.y * TILE_H;
    const int base = bz * NPIX;

    if (tid == 0) sN = 0;
    if (tid < NLAB) { sAF[tid] = 0.f; sAE[tid] = 0.f; }

    // Load (TILE_H+2) x 130 halo tiles of the 3 images
    for (int i = tid; i < (TILE_H+2) * 130; i += 256) {
        int lr = i / 130, lc = i - lr * 130;
        int gr = rowStart - 1 + lr, gc = colStart - 1 + lc;
        bool in = (gr >= 0) & (gr < HH) & (gc >= 0) & (gc < WW);
        int q = in ? base + gr * WW + gc : base;
        float fv = in ? vis[q] : 0.f;
        float ft = in ? th[q]  : 0.f;
        float fg = in ? gen[q] : 0.f;
        sV[lr][lc] = fv; sT[lr][lc] = ft; sG[lr][lc] = fg;
    }
    __syncthreads();

    // Build overlapping-box list for this tile (only boxes of this batch image)
    if (tid < NLAB) {
        const int* L = label + (bz * NLAB + tid) * 5;
        int x1 = L[1], y1 = L[2], x2 = L[3], y2 = L[4];
        if (x2 > x1 && y2 > y1 &&
            x1 < colStart + TILE_W && x2 > colStart &&
            y1 < rowStart + TILE_H && y2 > rowStart) {
            int p = atomicAdd(&sN, 1);
            sBox[p] = make_int4(x1, y1, x2, y2);
            sBoxIdx[p] = bz * NLAB + tid;
        }
    }
    __syncthreads();
    const int nOv = sN;

    const int lc0 = tx * 4;
    const int cbase = colStart + tx * 4;
    float li = 0.f, lg = 0.f;

    #pragma unroll
    for (int rr = 0; rr < 2; rr++) {
        const int ty2 = ty * 2 + rr;                  // output row within tile
        const int r = rowStart + ty2;

        G4 gv = sobel4(sV, ty2, lc0);
        G4 gt = sobel4(sT, ty2, lc0);
        G4 gg = sobel4(sG, ty2, lc0);

        float F[4], E[4];
        #pragma unroll
        for (int k = 0; k < 4; k++) {
            float gradV = fabsf(gv.gx[k]) + fabsf(gv.gy[k]);
            float gradG = fabsf(gg.gx[k]) + fabsf(gg.gy[k]);
            float g5 = fabsf(0.5f*(gv.gx[k] + gt.gx[k])) + fabsf(0.5f*(gv.gy[k] + gt.gy[k]));
            float g7 = fabsf(0.3f*gv.gx[k] + 0.7f*gt.gx[k]) + fabsf(0.3f*gv.gy[k] + 0.7f*gt.gy[k]);
            float xm  = 0.5f * (gv.c[k] + gt.c[k]);
            float xm7 = 0.3f * gv.c[k] + 0.7f * gt.c[k];
            li  += fabsf(gg.c[k] - fmaxf(gv.c[k], xm));
            lg  += fabsf(gradG - fmaxf(gradV, g5));
            F[k] = fabsf(gradG - fmaxf(gradV, g7));
            E[k] = fabsf(gg.c[k] - fmaxf(gv.c[k], xm7));
        }

        // Per-box accumulation: interior reuses F, ring pixels recompute masked sobel
        for (int b = 0; b < nOv; b++) {
            int4 B = sBox[b];
            float fb = 0.f, eb = 0.f;
            bool rowIn = (r >= B.y) & (r < B.w);
            if (rowIn) {
                bool rowInt = (r > B.y) & (r < B.w - 1);
                #pragma unroll
                for (int k = 0; k < 4; k++) {
                    int c = cbase + k;
                    if (c >= B.x && c < B.z) {
                        eb += E[k];
                        if (rowInt && c > B.x && c < B.z - 1) fb += F[k];
                        else fb += maskedF(sV, sT, sG, ty2, lc0 + k + 1, r, c, B);
                    }
                }
            }
            fb = wsum(fb); eb = wsum(eb);
            if ((tid & 31) == 0) { atomicAdd(&sAF[b], fb); atomicAdd(&sAE[b], eb); }
        }
    }

    // Reduce li/lg: warp sum + direct warp-leader global atomics (no smem stage)
    li = wsum(li); lg = wsum(lg);
    if ((tid & 31) == 0) {
        atomicAdd(&d_accIn[bz], li);
        atomicAdd(&d_accGrad[bz], lg);
    }
    __syncthreads();       // sAF/sAE complete before flush
    if (tid < nOv) {
        atomicAdd(&d_boxF[sBoxIdx[tid]], sAF[tid]);
        atomicAdd(&d_boxE[sBoxIdx[tid]], sAE[tid]);
    }

    // Last-block finalize
    __threadfence();
    __syncthreads();
    if (tid == 0) {
        unsigned o = atomicAdd(&d_count, 1u);
        sIsLast = (o == NBLOCKS - 1);
    }
    __syncthreads();
    if (!sIsLast) return;

    if (tid < BATCH * NLAB) {
        const int* L = label + tid * 5;
        int x1 = L[1], y1 = L[2], x2 = L[3], y2 = L[4];
        bool valid = !(x1 == 0 && y1 == 0 && x2 == 0 && y2 == 0);
        float area = (float)((y2 - y1) * (x2 - x1));       // C == 1
        float sa = fmaxf(area, 1.f);
        volatile float* vF = (volatile float*)d_boxF;
        volatile float* vE = (volatile float*)d_boxE;
        float f = vF[tid], e = vE[tid];
        float vv = valid ? 1.f : 0.f;
        sLs[tid] = (f / sa) * vv;
        sL1[tid] = (e / sa) * vv;
        d_boxF[tid] = 0.f; d_boxE[tid] = 0.f;              // reset for next replay
    }
    __syncthreads();
    if (tid < BATCH) {
        volatile float* aI = (volatile float*)d_accIn;
        volatile float* aG = (volatile float*)d_accGrad;
        const float inv = 1.0f / (float)NPIX;              // C == 1
        float loss_in   = aI[tid] * inv;
        float loss_grad = aG[tid] * inv;
        d_accIn[tid] = 0.f; d_accGrad[tid] = 0.f;          // reset

        float sLsum = 0.f, s1sum = 0.f, cnt = 0.f;
        for (int n = 0; n < NLAB; n++) {
            float a = sLs[tid * NLAB + n], bb = sL1[tid * NLAB + n];
            sLsum += a; s1sum += bb;
            if (a != 0.f || bb != 0.f) cnt += 1.f;
        }
        float safe_cnt = fmaxf(cnt, 1.f);
        float ls  = (cnt > 0.f) ? sLsum / safe_cnt : 0.f;
        float lin = (cnt > 0.f) ? s1sum / safe_cnt : 0.f;
        float alpha = *bptr, beta = *cptr;
        out[0*BATCH + tid] = 0.f;                                         // loss_ss
        out[1*BATCH + tid] = alpha * loss_in + (1.f - alpha) * loss_grad; // loss_global
        out[2*BATCH + tid] = (1.f - beta) * ls + beta * lin;              // loss_label
        out[3*BATCH + tid] = loss_in;
        out[4*BATCH + tid] = loss_grad;
        out[5*BATCH + tid] = ls;
        out[6*BATCH + tid] = lin;
    }
    if (tid == 0) d_count = 0;                                            // reset
}

extern "C" void kernel_launch(void* const* d_in, const int* in_sizes, int n_in,
                              void* d_out, int out_size)
{
    (void)in_sizes; (void)n_in; (void)out_size;
    const float* bptr  = (const float*)d_in[0];
    const float* cptr  = (const float*)d_in[1];
    const float* vis   = (const float*)d_in[2];
    // d_in[3] = image_ir (unused by the reference)
    const float* gen   = (const float*)d_in[4];
    const int*   label = (const int*)d_in[5];
    const float* th    = (const float*)d_in[6];
    float* out = (float*)d_out;

    dim3 grid(GXB, GYB, BATCH);
    dim3 blk(32, 8);
    fused_k<<<grid, blk>>>(vis, th, gen, label, bptr, cptr, out);
}